// round 1
// baseline (speedup 1.0000x reference)
#include <cuda_runtime.h>
#include <math.h>

#define NB 1024
#define NS 200
#define NH 256

// ---------------- scratch (device globals; no allocations allowed) ----------
static __device__ float g_att[NB * NS];                    // softmax attention [b][s]
static __device__ float g_gx[NS * NB * 768];               // precomputed x-part [s][b][768]
static __device__ float g_wxT[256 * 768];                  // x-part weights, k-major [k][i]
static __device__ float g_whru[256 * 512];                 // h-part (r,u) packed [(k>>2)][j][k&3]
static __device__ float g_whc[256 * 256];                  // h-part (c)  packed [(k>>2)][j][k&3]
static __device__ float g_wot[256 * 256];                  // Wo transposed packed [(k>>2)][j][k&3]

__device__ __forceinline__ float sigmoidf_(float x) { return 1.0f / (1.0f + expf(-x)); }

// ---------------- K0: weight repacking ---------------------------------------
__global__ void prep_kernel(const float* __restrict__ Wr, const float* __restrict__ Wu,
                            const float* __restrict__ Wc, const float* __restrict__ Wo)
{
    int idx = blockIdx.x * blockDim.x + threadIdx.x;
    if (idx < 196608) {
        // g_wxT[k][i] = W*[i][k]  (x-part: cols 0..255 of Wr/Wu/Wc)
        int k = idx / 768, i = idx - k * 768;
        float v;
        if (i < 256)      v = Wr[i * 512 + k];
        else if (i < 512) v = Wu[(i - 256) * 512 + k];
        else              v = Wc[(i - 512) * 512 + k];
        g_wxT[idx] = v;
    } else if (idx < 196608 + 131072) {
        int r = idx - 196608;
        int k = r / 512, j = r - k * 512;
        float v = (j < 256) ? Wr[j * 512 + 256 + k] : Wu[(j - 256) * 512 + 256 + k];
        g_whru[(k >> 2) * 2048 + j * 4 + (k & 3)] = v;
    } else if (idx < 196608 + 131072 + 65536) {
        int r = idx - (196608 + 131072);
        int k = r / 256, j = r - k * 256;
        g_whc[(k >> 2) * 1024 + j * 4 + (k & 3)] = Wc[j * 512 + 256 + k];
    } else if (idx < 196608 + 131072 + 131072) {
        int r = idx - (196608 + 131072 + 65536);
        int k = r / 256, j = r - k * 256;
        g_wot[(k >> 2) * 1024 + j * 4 + (k & 3)] = Wo[j * 256 + k];
    }
}

// ---------------- K1: attention softmax --------------------------------------
__global__ void __launch_bounds__(256) attn_kernel(const float* __restrict__ hist,
                                                   const float* __restrict__ tgt,
                                                   const int* __restrict__ mask)
{
    __shared__ float tg[256];
    __shared__ float lg[200];
    __shared__ float red[8];
    int b = blockIdx.x;
    int t = threadIdx.x;
    int lane = t & 31, w = t >> 5;
    tg[t] = tgt[b * 256 + t];
    __syncthreads();
    for (int s = w; s < 200; s += 8) {
        const float* hp = hist + ((size_t)(b * 200 + s)) * 256;
        float acc = 0.0f;
        #pragma unroll
        for (int i = 0; i < 8; i++) acc += hp[lane + 32 * i] * tg[lane + 32 * i];
        #pragma unroll
        for (int o = 16; o > 0; o >>= 1) acc += __shfl_xor_sync(0xffffffffu, acc, o);
        if (lane == 0)
            lg[s] = (mask[b * 200 + s] == 0) ? -1.0e9f : acc * 0.0625f; // 1/sqrt(256)
    }
    __syncthreads();
    float v = (t < 200) ? lg[t] : -3.0e38f;
    float m = v;
    #pragma unroll
    for (int o = 16; o > 0; o >>= 1) m = fmaxf(m, __shfl_xor_sync(0xffffffffu, m, o));
    if (lane == 0) red[w] = m;
    __syncthreads();
    if (t == 0) {
        float mm = red[0];
        for (int i = 1; i < 8; i++) mm = fmaxf(mm, red[i]);
        red[0] = mm;
    }
    __syncthreads();
    float mx = red[0];
    float e = (t < 200) ? expf(v - mx) : 0.0f;
    __syncthreads();
    float ssum = e;
    #pragma unroll
    for (int o = 16; o > 0; o >>= 1) ssum += __shfl_xor_sync(0xffffffffu, ssum, o);
    if (lane == 0) red[w] = ssum;
    __syncthreads();
    if (t == 0) {
        float tt = 0.0f;
        for (int i = 0; i < 8; i++) tt += red[i];
        red[0] = tt;
    }
    __syncthreads();
    if (t < 200) g_att[b * 200 + t] = e / red[0];
}

// ---------------- K2: Gx = hist @ WxT + bias  (M=204800,K=256,N=768) ---------
__global__ void __launch_bounds__(256) gx_gemm_kernel(const float* __restrict__ A,
                                                      const float* __restrict__ br,
                                                      const float* __restrict__ bu,
                                                      const float* __restrict__ bc)
{
    __shared__ __align__(16) float As[16 * 132];
    __shared__ __align__(16) float Bs[16 * 132];
    int m0 = blockIdx.x * 128;
    int n0 = blockIdx.y * 128;
    int t = threadIdx.x;
    int tx = t & 15, ty = t >> 4;
    float acc[8][8];
    #pragma unroll
    for (int i = 0; i < 8; i++)
        #pragma unroll
        for (int j = 0; j < 8; j++) acc[i][j] = 0.0f;

    int la_row = t >> 2;          // 0..63
    int la_c = (t & 3) * 4;       // k offset within chunk
    int lb_row = t >> 5;          // 0..7
    int lb_c = (t & 31) * 4;

    for (int kc = 0; kc < 256; kc += 16) {
        float4 a0 = *(const float4*)(A + (size_t)(m0 + la_row) * 256 + kc + la_c);
        float4 a1 = *(const float4*)(A + (size_t)(m0 + la_row + 64) * 256 + kc + la_c);
        float4 b0 = *(const float4*)(g_wxT + (kc + lb_row) * 768 + n0 + lb_c);
        float4 b1 = *(const float4*)(g_wxT + (kc + lb_row + 8) * 768 + n0 + lb_c);
        __syncthreads();
        As[(la_c + 0) * 132 + la_row] = a0.x;
        As[(la_c + 1) * 132 + la_row] = a0.y;
        As[(la_c + 2) * 132 + la_row] = a0.z;
        As[(la_c + 3) * 132 + la_row] = a0.w;
        As[(la_c + 0) * 132 + la_row + 64] = a1.x;
        As[(la_c + 1) * 132 + la_row + 64] = a1.y;
        As[(la_c + 2) * 132 + la_row + 64] = a1.z;
        As[(la_c + 3) * 132 + la_row + 64] = a1.w;
        *(float4*)&Bs[lb_row * 132 + lb_c] = b0;
        *(float4*)&Bs[(lb_row + 8) * 132 + lb_c] = b1;
        __syncthreads();
        #pragma unroll
        for (int k = 0; k < 16; k++) {
            float af[8], bf[8];
            *(float4*)(af)     = *(const float4*)&As[k * 132 + ty * 8];
            *(float4*)(af + 4) = *(const float4*)&As[k * 132 + ty * 8 + 4];
            *(float4*)(bf)     = *(const float4*)&Bs[k * 132 + tx * 8];
            *(float4*)(bf + 4) = *(const float4*)&Bs[k * 132 + tx * 8 + 4];
            #pragma unroll
            for (int i = 0; i < 8; i++)
                #pragma unroll
                for (int j = 0; j < 8; j++)
                    acc[i][j] += af[i] * bf[j];
        }
    }
    float bias[8];
    int nb = n0 + tx * 8;
    #pragma unroll
    for (int j = 0; j < 8; j++) {
        int n = nb + j;
        bias[j] = (n < 256) ? br[n] : (n < 512) ? bu[n - 256] : bc[n - 512];
    }
    #pragma unroll
    for (int i = 0; i < 8; i++) {
        int m = m0 + ty * 8 + i;
        int b = m / 200, s = m - b * 200;
        float* dst = g_gx + ((size_t)s * NB + b) * 768 + nb;
        float4 o0 = make_float4(acc[i][0] + bias[0], acc[i][1] + bias[1],
                                acc[i][2] + bias[2], acc[i][3] + bias[3]);
        float4 o1 = make_float4(acc[i][4] + bias[4], acc[i][5] + bias[5],
                                acc[i][6] + bias[6], acc[i][7] + bias[7]);
        *(float4*)dst = o0;
        *(float4*)(dst + 4) = o1;
    }
}

// ---------------- K3: persistent sequential GRU scan -------------------------
// 128 CTAs x 512 threads; CTA owns 8 batch rows, h in SMEM, no cross-CTA comm.
__global__ void __launch_bounds__(512, 1) gru_kernel(const int* __restrict__ mask,
                                                     const float* __restrict__ bo,
                                                     float* __restrict__ out)
{
    __shared__ __align__(16) float h_s[8][256];
    __shared__ __align__(16) float rh_s[8][256];
    __shared__ float u_s[8][256];
    __shared__ float a_s[8];
    __shared__ int   m_s[8];
    int b0 = blockIdx.x * 8;
    int t = threadIdx.x;
    int jc = t & 255;
    int rbase = (t >> 8) * 4;

    for (int i = t; i < 8 * 256; i += 512) (&h_s[0][0])[i] = 0.0f;
    float pool[4];
    #pragma unroll
    for (int i = 0; i < 4; i++) pool[i] = -3.0e38f;
    __syncthreads();

    for (int s = 0; s < 200; s++) {
        if (t < 8) {
            a_s[t] = g_att[(b0 + t) * NS + s];
            m_s[t] = mask[(b0 + t) * NS + s];
        }
        // GEMM1: pre_{r,u}[rb][t] = sum_k h[rb][k] * Whru[k][t]
        float acc[8];
        #pragma unroll
        for (int i = 0; i < 8; i++) acc[i] = 0.0f;
        #pragma unroll 4
        for (int k4 = 0; k4 < 64; k4++) {
            float4 wv = *(const float4*)(g_whru + k4 * 2048 + t * 4);
            #pragma unroll
            for (int rb = 0; rb < 8; rb++) {
                float4 hv = *(const float4*)(&h_s[rb][k4 * 4]);
                acc[rb] += hv.x * wv.x + hv.y * wv.y + hv.z * wv.z + hv.w * wv.w;
            }
        }
        const float* gxp = g_gx + ((size_t)s * NB + b0) * 768 + t;
        if (t < 256) {
            #pragma unroll
            for (int rb = 0; rb < 8; rb++) {
                float r = sigmoidf_(acc[rb] + gxp[rb * 768]);
                rh_s[rb][t] = r * h_s[rb][t];
            }
        } else {
            #pragma unroll
            for (int rb = 0; rb < 8; rb++)
                u_s[rb][jc] = sigmoidf_(acc[rb] + gxp[rb * 768]);
        }
        __syncthreads();
        // GEMM2: pre_c[rb][jc] = sum_k rh[rb][k] * Whc[k][jc]   (4 rows per thread)
        float acc2[4];
        #pragma unroll
        for (int i = 0; i < 4; i++) acc2[i] = 0.0f;
        #pragma unroll 4
        for (int k4 = 0; k4 < 64; k4++) {
            float4 wv = *(const float4*)(g_whc + k4 * 1024 + jc * 4);
            #pragma unroll
            for (int i = 0; i < 4; i++) {
                float4 hv = *(const float4*)(&rh_s[rbase + i][k4 * 4]);
                acc2[i] += hv.x * wv.x + hv.y * wv.y + hv.z * wv.z + hv.w * wv.w;
            }
        }
        const float* gxp2 = g_gx + ((size_t)s * NB + b0 + rbase) * 768 + 512 + jc;
        #pragma unroll
        for (int i = 0; i < 4; i++) {
            int rb = rbase + i;
            float c = tanhf(acc2[i] + gxp2[i * 768]);
            float uu = a_s[rb] * u_s[rb][jc];
            float hn = (1.0f - uu) * h_s[rb][jc] + uu * c;
            h_s[rb][jc] = hn;
            pool[i] = fmaxf(pool[i], m_s[rb] ? hn : 0.0f);
        }
        __syncthreads();
    }

    // epilogue: last-h + masked-max-pool @ Wo^T + bo
    #pragma unroll
    for (int i = 0; i < 4; i++) rh_s[rbase + i][jc] = pool[i];
    __syncthreads();
    if (t < 256) {
        #pragma unroll
        for (int rb = 0; rb < 8; rb++)
            out[(size_t)(b0 + rb) * 512 + t] = h_s[rb][t];
        float acc3[8];
        #pragma unroll
        for (int i = 0; i < 8; i++) acc3[i] = 0.0f;
        #pragma unroll 4
        for (int k4 = 0; k4 < 64; k4++) {
            float4 wv = *(const float4*)(g_wot + k4 * 1024 + t * 4);
            #pragma unroll
            for (int rb = 0; rb < 8; rb++) {
                float4 hv = *(const float4*)(&rh_s[rb][k4 * 4]);
                acc3[rb] += hv.x * wv.x + hv.y * wv.y + hv.z * wv.z + hv.w * wv.w;
            }
        }
        float bb = bo[t];
        #pragma unroll
        for (int rb = 0; rb < 8; rb++)
            out[(size_t)(b0 + rb) * 512 + 256 + t] = acc3[rb] + bb;
    }
}

// ---------------- launch ------------------------------------------------------
extern "C" void kernel_launch(void* const* d_in, const int* in_sizes, int n_in,
                              void* d_out, int out_size)
{
    const float* hist = (const float*)d_in[0];
    const float* tgt  = (const float*)d_in[1];
    const int*   mask = (const int*)d_in[2];
    const float* Wr   = (const float*)d_in[3];
    const float* br   = (const float*)d_in[4];
    const float* Wu   = (const float*)d_in[5];
    const float* bu   = (const float*)d_in[6];
    const float* Wc   = (const float*)d_in[7];
    const float* bc   = (const float*)d_in[8];
    const float* Wo   = (const float*)d_in[9];
    const float* bo   = (const float*)d_in[10];
    float* out = (float*)d_out;

    prep_kernel<<<1792, 256>>>(Wr, Wu, Wc, Wo);
    attn_kernel<<<NB, 256>>>(hist, tgt, mask);
    gx_gemm_kernel<<<dim3(1600, 6), 256>>>(hist, br, bu, bc);
    gru_kernel<<<128, 512>>>(mask, bo, out);
}